// round 9
// baseline (speedup 1.0000x reference)
#include <cuda_runtime.h>
#include <cuda_bf16.h>
#include <cstdint>

constexpr int B = 2, C = 2, D = 160, H = 192, W = 224;
constexpr int HW  = H * W;          // 43008
constexpr int DHW = D * H * W;      // 6,881,280

__global__ __launch_bounds__(224)
void affine_grid_sample_kernel(const float* __restrict__ src,
                               const float* __restrict__ mat,
                               float* __restrict__ out)
{
    const int w  = threadIdx.x;      // 0..W-1
    const int h  = blockIdx.y;       // 0..H-1
    const int zz = blockIdx.z;       // 0..B*D-1
    const int b  = (zz >= D) ? 1 : 0;
    const int d  = zz - (b ? D : 0);

    const float4* m4 = (const float4*)(mat + b * 12);
    const float4 r0 = __ldg(m4 + 0);
    const float4 r1 = __ldg(m4 + 1);
    const float4 r2 = __ldg(m4 + 2);

    // normalized coords (align_corners=True)
    const float x = fmaf((float)w, 2.0f / (W - 1), -1.0f);
    const float y = fmaf((float)h, 2.0f / (H - 1), -1.0f);
    const float z = fmaf((float)d, 2.0f / (D - 1), -1.0f);

    // theta = mat with translation column scaled by 1/{D,H,W} per row
    const float gx = fmaf(r0.x, x, fmaf(r0.y, y, fmaf(r0.z, z, r0.w * (1.0f / D))));
    const float gy = fmaf(r1.x, x, fmaf(r1.y, y, fmaf(r1.z, z, r1.w * (1.0f / H))));
    const float gz = fmaf(r2.x, x, fmaf(r2.y, y, fmaf(r2.z, z, r2.w * (1.0f / W))));

    // unnormalize
    const float ix = (gx + 1.0f) * (0.5f * (W - 1));
    const float iy = (gy + 1.0f) * (0.5f * (H - 1));
    const float iz = (gz + 1.0f) * (0.5f * (D - 1));

    const float fx0 = floorf(ix), fy0 = floorf(iy), fz0 = floorf(iz);
    const float fx = ix - fx0, fy = iy - fy0, fz = iz - fz0;
    const int x0 = (int)fx0, y0 = (int)fy0, z0 = (int)fz0;

    // validity per axis (unsigned-compare trick handles negatives)
    const bool vx0 = (unsigned)x0       < (unsigned)W;
    const bool vx1 = (unsigned)(x0 + 1) < (unsigned)W;
    const bool vy0 = (unsigned)y0       < (unsigned)H;
    const bool vy1 = (unsigned)(y0 + 1) < (unsigned)H;
    const bool vz0 = (unsigned)z0       < (unsigned)D;
    const bool vz1 = (unsigned)(z0 + 1) < (unsigned)D;

    // trilinear weights
    const float wx1 = fx, wx0 = 1.0f - fx;
    const float wy1 = fy, wy0 = 1.0f - fy;
    const float wz1 = fz, wz0 = 1.0f - fz;
    const float w00 = wz0 * wy0, w01 = wz0 * wy1;
    const float w10 = wz1 * wy0, w11 = wz1 * wy1;
    const float w000 = w00 * wx0, w001 = w00 * wx1;
    const float w010 = w01 * wx0, w011 = w01 * wx1;
    const float w100 = w10 * wx0, w101 = w10 * wx1;
    const float w110 = w11 * wx0, w111 = w11 * wx1;

    const float* sb = src + (size_t)b * (size_t)(C * DHW);
    const float* p  = sb + ((size_t)((z0 * H + y0) * W + x0));

    const bool p000 = vz0 & vy0 & vx0, p001 = vz0 & vy0 & vx1;
    const bool p010 = vz0 & vy1 & vx0, p011 = vz0 & vy1 & vx1;
    const bool p100 = vz1 & vy0 & vx0, p101 = vz1 & vy0 & vx1;
    const bool p110 = vz1 & vy1 & vx0, p111 = vz1 & vy1 & vx1;

    // channel 0
    float a000 = p000 ? __ldg(p)              : 0.0f;
    float a001 = p001 ? __ldg(p + 1)          : 0.0f;
    float a010 = p010 ? __ldg(p + W)          : 0.0f;
    float a011 = p011 ? __ldg(p + W + 1)      : 0.0f;
    float a100 = p100 ? __ldg(p + HW)         : 0.0f;
    float a101 = p101 ? __ldg(p + HW + 1)     : 0.0f;
    float a110 = p110 ? __ldg(p + HW + W)     : 0.0f;
    float a111 = p111 ? __ldg(p + HW + W + 1) : 0.0f;
    // channel 1 (same taps, +DHW)
    const float* q = p + DHW;
    float c000 = p000 ? __ldg(q)              : 0.0f;
    float c001 = p001 ? __ldg(q + 1)          : 0.0f;
    float c010 = p010 ? __ldg(q + W)          : 0.0f;
    float c011 = p011 ? __ldg(q + W + 1)      : 0.0f;
    float c100 = p100 ? __ldg(q + HW)         : 0.0f;
    float c101 = p101 ? __ldg(q + HW + 1)     : 0.0f;
    float c110 = p110 ? __ldg(q + HW + W)     : 0.0f;
    float c111 = p111 ? __ldg(q + HW + W + 1) : 0.0f;

    float acc0 = w000 * a000;
    acc0 = fmaf(w001, a001, acc0);
    acc0 = fmaf(w010, a010, acc0);
    acc0 = fmaf(w011, a011, acc0);
    acc0 = fmaf(w100, a100, acc0);
    acc0 = fmaf(w101, a101, acc0);
    acc0 = fmaf(w110, a110, acc0);
    acc0 = fmaf(w111, a111, acc0);

    float acc1 = w000 * c000;
    acc1 = fmaf(w001, c001, acc1);
    acc1 = fmaf(w010, c010, acc1);
    acc1 = fmaf(w011, c011, acc1);
    acc1 = fmaf(w100, c100, acc1);
    acc1 = fmaf(w101, c101, acc1);
    acc1 = fmaf(w110, c110, acc1);
    acc1 = fmaf(w111, c111, acc1);

    // streaming stores: output is never re-read; keep it out of L2
    const size_t ob = (size_t)b * (size_t)(C * DHW) + (size_t)((d * H + h) * W + w);
    __stcs(out + ob,       acc0);
    __stcs(out + ob + DHW, acc1);
}

extern "C" void kernel_launch(void* const* d_in, const int* in_sizes, int n_in,
                              void* d_out, int out_size)
{
    const float* src = (const float*)d_in[0];
    const float* mat = (const float*)d_in[1];
    float* out = (float*)d_out;

    // smem unused: hand the full unified carveout to L1D
    cudaFuncSetAttribute(affine_grid_sample_kernel,
                         cudaFuncAttributePreferredSharedMemoryCarveout,
                         cudaSharedmemCarveoutMaxL1);

    dim3 block(W, 1, 1);          // 224 threads = 7 warps (round-2 champion config)
    dim3 grid(1, H, B * D);       // (1, 192, 320)
    affine_grid_sample_kernel<<<grid, block>>>(src, mat, out);
}

// round 10
// speedup vs baseline: 1.0043x; 1.0043x over previous
#include <cuda_runtime.h>
#include <cuda_bf16.h>
#include <cstdint>

constexpr int B = 2, C = 2, D = 160, H = 192, W = 224;
constexpr int HW  = H * W;          // 43008
constexpr int DHW = D * H * W;      // 6,881,280

struct Coord {
    int x0, y0, z0;
    float w000, w001, w010, w011, w100, w101, w110, w111;
    bool interior;
};

__device__ __forceinline__ Coord make_coord(float4 r0, float4 r1, float4 r2,
                                            int w, int h, int d)
{
    const float x = fmaf((float)w, 2.0f / (W - 1), -1.0f);
    const float y = fmaf((float)h, 2.0f / (H - 1), -1.0f);
    const float z = fmaf((float)d, 2.0f / (D - 1), -1.0f);

    const float gx = fmaf(r0.x, x, fmaf(r0.y, y, fmaf(r0.z, z, r0.w * (1.0f / D))));
    const float gy = fmaf(r1.x, x, fmaf(r1.y, y, fmaf(r1.z, z, r1.w * (1.0f / H))));
    const float gz = fmaf(r2.x, x, fmaf(r2.y, y, fmaf(r2.z, z, r2.w * (1.0f / W))));

    const float ix = (gx + 1.0f) * (0.5f * (W - 1));
    const float iy = (gy + 1.0f) * (0.5f * (H - 1));
    const float iz = (gz + 1.0f) * (0.5f * (D - 1));

    const float fx0 = floorf(ix), fy0 = floorf(iy), fz0 = floorf(iz);
    const float fx = ix - fx0, fy = iy - fy0, fz = iz - fz0;

    Coord c;
    c.x0 = (int)fx0; c.y0 = (int)fy0; c.z0 = (int)fz0;

    const float wx1 = fx, wx0 = 1.0f - fx;
    const float wy1 = fy, wy0 = 1.0f - fy;
    const float wz1 = fz, wz0 = 1.0f - fz;
    const float w00 = wz0 * wy0, w01 = wz0 * wy1;
    const float w10 = wz1 * wy0, w11 = wz1 * wy1;
    c.w000 = w00 * wx0; c.w001 = w00 * wx1;
    c.w010 = w01 * wx0; c.w011 = w01 * wx1;
    c.w100 = w10 * wx0; c.w101 = w10 * wx1;
    c.w110 = w11 * wx0; c.w111 = w11 * wx1;

    c.interior = ((unsigned)c.x0 < (unsigned)(W - 1)) &
                 ((unsigned)c.y0 < (unsigned)(H - 1)) &
                 ((unsigned)c.z0 < (unsigned)(D - 1));
    return c;
}

// fully-predicated (zero-pad) sample of both channels — slow path
__device__ __forceinline__ void sample_pred(const float* __restrict__ sb,
                                            const Coord& c,
                                            float& acc0, float& acc1)
{
    const bool vx0 = (unsigned)c.x0       < (unsigned)W;
    const bool vx1 = (unsigned)(c.x0 + 1) < (unsigned)W;
    const bool vy0 = (unsigned)c.y0       < (unsigned)H;
    const bool vy1 = (unsigned)(c.y0 + 1) < (unsigned)H;
    const bool vz0 = (unsigned)c.z0       < (unsigned)D;
    const bool vz1 = (unsigned)(c.z0 + 1) < (unsigned)D;

    const bool p000 = vz0 & vy0 & vx0, p001 = vz0 & vy0 & vx1;
    const bool p010 = vz0 & vy1 & vx0, p011 = vz0 & vy1 & vx1;
    const bool p100 = vz1 & vy0 & vx0, p101 = vz1 & vy0 & vx1;
    const bool p110 = vz1 & vy1 & vx0, p111 = vz1 & vy1 & vx1;

    const float* p = sb + ((size_t)((c.z0 * H + c.y0) * W + c.x0));
    const float* q = p + DHW;

    float a000 = p000 ? __ldg(p)              : 0.0f;
    float a001 = p001 ? __ldg(p + 1)          : 0.0f;
    float a010 = p010 ? __ldg(p + W)          : 0.0f;
    float a011 = p011 ? __ldg(p + W + 1)      : 0.0f;
    float a100 = p100 ? __ldg(p + HW)         : 0.0f;
    float a101 = p101 ? __ldg(p + HW + 1)     : 0.0f;
    float a110 = p110 ? __ldg(p + HW + W)     : 0.0f;
    float a111 = p111 ? __ldg(p + HW + W + 1) : 0.0f;
    float c000 = p000 ? __ldg(q)              : 0.0f;
    float c001 = p001 ? __ldg(q + 1)          : 0.0f;
    float c010 = p010 ? __ldg(q + W)          : 0.0f;
    float c011 = p011 ? __ldg(q + W + 1)      : 0.0f;
    float c100 = p100 ? __ldg(q + HW)         : 0.0f;
    float c101 = p101 ? __ldg(q + HW + 1)     : 0.0f;
    float c110 = p110 ? __ldg(q + HW + W)     : 0.0f;
    float c111 = p111 ? __ldg(q + HW + W + 1) : 0.0f;

    acc0 = c.w000 * a000;
    acc0 = fmaf(c.w001, a001, acc0);
    acc0 = fmaf(c.w010, a010, acc0);
    acc0 = fmaf(c.w011, a011, acc0);
    acc0 = fmaf(c.w100, a100, acc0);
    acc0 = fmaf(c.w101, a101, acc0);
    acc0 = fmaf(c.w110, a110, acc0);
    acc0 = fmaf(c.w111, a111, acc0);

    acc1 = c.w000 * c000;
    acc1 = fmaf(c.w001, c001, acc1);
    acc1 = fmaf(c.w010, c010, acc1);
    acc1 = fmaf(c.w011, c011, acc1);
    acc1 = fmaf(c.w100, c100, acc1);
    acc1 = fmaf(c.w101, c101, acc1);
    acc1 = fmaf(c.w110, c110, acc1);
    acc1 = fmaf(c.w111, c111, acc1);
}

__global__ __launch_bounds__(224)
void affine_grid_sample_kernel(const float* __restrict__ src,
                               const float* __restrict__ mat,
                               float* __restrict__ out)
{
    const int w  = threadIdx.x;      // 0..W-1
    const int h  = blockIdx.y;       // 0..H-1
    const int zz = blockIdx.z;       // 0..B*(D/2)-1
    const int b  = (zz >= D / 2) ? 1 : 0;
    const int d0 = 2 * (zz - (b ? D / 2 : 0));   // even d; thread does d0 and d0+1

    const float4* m4 = (const float4*)(mat + b * 12);
    const float4 r0 = __ldg(m4 + 0);
    const float4 r1 = __ldg(m4 + 1);
    const float4 r2 = __ldg(m4 + 2);

    const Coord A = make_coord(r0, r1, r2, w, h, d0);
    const Coord Bc = make_coord(r0, r1, r2, w, h, d0 + 1);

    const float* sb = src + (size_t)b * (size_t)(C * DHW);

    float accA0, accA1, accB0, accB1;

    if (A.interior & Bc.interior) {
        // ---- voxel A: full 16 taps ----
        const float* p = sb + ((size_t)((A.z0 * H + A.y0) * W + A.x0));
        const float* q = p + DHW;

        float a000 = __ldg(p);
        float a001 = __ldg(p + 1);
        float a010 = __ldg(p + W);
        float a011 = __ldg(p + W + 1);
        float a100 = __ldg(p + HW);
        float a101 = __ldg(p + HW + 1);
        float a110 = __ldg(p + HW + W);
        float a111 = __ldg(p + HW + W + 1);
        float c000 = __ldg(q);
        float c001 = __ldg(q + 1);
        float c010 = __ldg(q + W);
        float c011 = __ldg(q + W + 1);
        float c100 = __ldg(q + HW);
        float c101 = __ldg(q + HW + 1);
        float c110 = __ldg(q + HW + W);
        float c111 = __ldg(q + HW + W + 1);

        // ---- voxel B: upper plane always loaded (z = zB0+1) ----
        const float* pb = sb + ((size_t)((Bc.z0 * H + Bc.y0) * W + Bc.x0));
        const float* qb = pb + DHW;

        float b100 = __ldg(pb + HW);
        float b101 = __ldg(pb + HW + 1);
        float b110 = __ldg(pb + HW + W);
        float b111 = __ldg(pb + HW + W + 1);
        float e100 = __ldg(qb + HW);
        float e101 = __ldg(qb + HW + 1);
        float e110 = __ldg(qb + HW + W);
        float e111 = __ldg(qb + HW + W + 1);

        // B's lower plane == A's upper plane when base coords line up (~85-90%)
        const bool sh = (Bc.z0 == A.z0 + 1) & (Bc.y0 == A.y0) & (Bc.x0 == A.x0);

        float b000 = sh ? a100 : __ldg(pb);
        float b001 = sh ? a101 : __ldg(pb + 1);
        float b010 = sh ? a110 : __ldg(pb + W);
        float b011 = sh ? a111 : __ldg(pb + W + 1);
        float e000 = sh ? c100 : __ldg(qb);
        float e001 = sh ? c101 : __ldg(qb + 1);
        float e010 = sh ? c110 : __ldg(qb + W);
        float e011 = sh ? c111 : __ldg(qb + W + 1);

        accA0 = A.w000 * a000;
        accA0 = fmaf(A.w001, a001, accA0);
        accA0 = fmaf(A.w010, a010, accA0);
        accA0 = fmaf(A.w011, a011, accA0);
        accA0 = fmaf(A.w100, a100, accA0);
        accA0 = fmaf(A.w101, a101, accA0);
        accA0 = fmaf(A.w110, a110, accA0);
        accA0 = fmaf(A.w111, a111, accA0);

        accA1 = A.w000 * c000;
        accA1 = fmaf(A.w001, c001, accA1);
        accA1 = fmaf(A.w010, c010, accA1);
        accA1 = fmaf(A.w011, c011, accA1);
        accA1 = fmaf(A.w100, c100, accA1);
        accA1 = fmaf(A.w101, c101, accA1);
        accA1 = fmaf(A.w110, c110, accA1);
        accA1 = fmaf(A.w111, c111, accA1);

        accB0 = Bc.w000 * b000;
        accB0 = fmaf(Bc.w001, b001, accB0);
        accB0 = fmaf(Bc.w010, b010, accB0);
        accB0 = fmaf(Bc.w011, b011, accB0);
        accB0 = fmaf(Bc.w100, b100, accB0);
        accB0 = fmaf(Bc.w101, b101, accB0);
        accB0 = fmaf(Bc.w110, b110, accB0);
        accB0 = fmaf(Bc.w111, b111, accB0);

        accB1 = Bc.w000 * e000;
        accB1 = fmaf(Bc.w001, e001, accB1);
        accB1 = fmaf(Bc.w010, e010, accB1);
        accB1 = fmaf(Bc.w011, e011, accB1);
        accB1 = fmaf(Bc.w100, e100, accB1);
        accB1 = fmaf(Bc.w101, e101, accB1);
        accB1 = fmaf(Bc.w110, e110, accB1);
        accB1 = fmaf(Bc.w111, e111, accB1);
    } else {
        sample_pred(sb, A,  accA0, accA1);
        sample_pred(sb, Bc, accB0, accB1);
    }

    const size_t obA = (size_t)b * (size_t)(C * DHW) + (size_t)((d0 * H + h) * W + w);
    out[obA]            = accA0;
    out[obA + DHW]      = accA1;
    out[obA + HW]       = accB0;   // voxel B is d0+1 -> +HW in spatial index
    out[obA + HW + DHW] = accB1;
}

extern "C" void kernel_launch(void* const* d_in, const int* in_sizes, int n_in,
                              void* d_out, int out_size)
{
    const float* src = (const float*)d_in[0];
    const float* mat = (const float*)d_in[1];
    float* out = (float*)d_out;

    dim3 block(W, 1, 1);              // 224 threads = 7 warps
    dim3 grid(1, H, B * (D / 2));     // (1, 192, 160)
    affine_grid_sample_kernel<<<grid, block>>>(src, mat, out);
}

// round 11
// speedup vs baseline: 1.1651x; 1.1601x over previous
#include <cuda_runtime.h>
#include <cuda_bf16.h>
#include <cstdint>

constexpr int B = 2, C = 2, D = 160, H = 192, W = 224;
constexpr int HW  = H * W;          // 43008
constexpr int DHW = D * H * W;      // 6,881,280

__device__ __forceinline__ float lerpf(float a, float b, float t) {
    return fmaf(t, b - a, a);
}

__global__ __launch_bounds__(224, 7)
void affine_grid_sample_kernel(const float* __restrict__ src,
                               const float* __restrict__ mat,
                               float* __restrict__ out)
{
    const int w  = threadIdx.x;      // 0..W-1
    const int h  = blockIdx.y;       // 0..H-1
    const int zz = blockIdx.z;       // 0..B*(D/2)-1
    const int b  = (zz >= D / 2) ? 1 : 0;
    const int d0 = 2 * (zz - (b ? D / 2 : 0));   // this thread does d0 and d0+1

    const float4* m4 = (const float4*)(mat + b * 12);
    const float4 r0 = __ldg(m4 + 0);
    const float4 r1 = __ldg(m4 + 1);
    const float4 r2 = __ldg(m4 + 2);

    // voxel A (d0) coordinates, round-2 formulation
    const float x = fmaf((float)w,  2.0f / (W - 1), -1.0f);
    const float y = fmaf((float)h,  2.0f / (H - 1), -1.0f);
    const float z = fmaf((float)d0, 2.0f / (D - 1), -1.0f);

    const float gxA = fmaf(r0.x, x, fmaf(r0.y, y, fmaf(r0.z, z, r0.w * (1.0f / D))));
    const float gyA = fmaf(r1.x, x, fmaf(r1.y, y, fmaf(r1.z, z, r1.w * (1.0f / H))));
    const float gzA = fmaf(r2.x, x, fmaf(r2.y, y, fmaf(r2.z, z, r2.w * (1.0f / W))));

    const float ixA = (gxA + 1.0f) * (0.5f * (W - 1));
    const float iyA = (gyA + 1.0f) * (0.5f * (H - 1));
    const float izA = (gzA + 1.0f) * (0.5f * (D - 1));

    // voxel B (d0+1) = A + constant z-step delta
    const float ddz = 2.0f / (D - 1);
    const float ixB = fmaf(r0.z, ddz * (0.5f * (W - 1)), ixA);
    const float iyB = fmaf(r1.z, ddz * (0.5f * (H - 1)), iyA);
    const float izB = fmaf(r2.z, ddz * (0.5f * (D - 1)), izA);

    const float fxA0 = floorf(ixA), fyA0 = floorf(iyA), fzA0 = floorf(izA);
    const float fxB0 = floorf(ixB), fyB0 = floorf(iyB), fzB0 = floorf(izB);
    const float fxA = ixA - fxA0, fyA = iyA - fyA0, fzA = izA - fzA0;
    const float fxB = ixB - fxB0, fyB = iyB - fyB0, fzB = izB - fzB0;
    const int xA0 = (int)fxA0, yA0 = (int)fyA0, zA0 = (int)fzA0;
    const int xB0 = (int)fxB0, yB0 = (int)fyB0, zB0 = (int)fzB0;

    // per-axis validity
    const bool vAx0 = (unsigned)xA0       < (unsigned)W;
    const bool vAx1 = (unsigned)(xA0 + 1) < (unsigned)W;
    const bool vAy0 = (unsigned)yA0       < (unsigned)H;
    const bool vAy1 = (unsigned)(yA0 + 1) < (unsigned)H;
    const bool vAz0 = (unsigned)zA0       < (unsigned)D;
    const bool vAz1 = (unsigned)(zA0 + 1) < (unsigned)D;
    const bool vBx0 = (unsigned)xB0       < (unsigned)W;
    const bool vBx1 = (unsigned)(xB0 + 1) < (unsigned)W;
    const bool vBy0 = (unsigned)yB0       < (unsigned)H;
    const bool vBy1 = (unsigned)(yB0 + 1) < (unsigned)H;
    const bool vBz0 = (unsigned)zB0       < (unsigned)D;
    const bool vBz1 = (unsigned)(zB0 + 1) < (unsigned)D;

    const bool pA000 = vAz0 & vAy0 & vAx0, pA001 = vAz0 & vAy0 & vAx1;
    const bool pA010 = vAz0 & vAy1 & vAx0, pA011 = vAz0 & vAy1 & vAx1;
    const bool pA100 = vAz1 & vAy0 & vAx0, pA101 = vAz1 & vAy0 & vAx1;
    const bool pA110 = vAz1 & vAy1 & vAx0, pA111 = vAz1 & vAy1 & vAx1;
    const bool pB000 = vBz0 & vBy0 & vBx0, pB001 = vBz0 & vBy0 & vBx1;
    const bool pB010 = vBz0 & vBy1 & vBx0, pB011 = vBz0 & vBy1 & vBx1;
    const bool pB100 = vBz1 & vBy0 & vBx0, pB101 = vBz1 & vBy0 & vBx1;
    const bool pB110 = vBz1 & vBy1 & vBx0, pB111 = vBz1 & vBy1 & vBx1;

    // B's lower plane coincides with A's upper plane (incl. validity) when:
    const bool sh = (zB0 == zA0 + 1) & (yB0 == yA0) & (xB0 == xA0);

    const float* sb = src + (size_t)b * (size_t)(C * DHW);
    const float* pA = sb + ((size_t)((zA0 * H + yA0) * W + xA0));
    const float* pB = sb + ((size_t)((zB0 * H + yB0) * W + xB0));

    const size_t obA = (size_t)b * (size_t)(C * DHW) + (size_t)((d0 * H + h) * W + w);

    // ================= phase 0: channel 0 =================
    {
        float a000 = pA000 ? __ldg(pA)              : 0.0f;
        float a001 = pA001 ? __ldg(pA + 1)          : 0.0f;
        float a010 = pA010 ? __ldg(pA + W)          : 0.0f;
        float a011 = pA011 ? __ldg(pA + W + 1)      : 0.0f;
        float a100 = pA100 ? __ldg(pA + HW)         : 0.0f;
        float a101 = pA101 ? __ldg(pA + HW + 1)     : 0.0f;
        float a110 = pA110 ? __ldg(pA + HW + W)     : 0.0f;
        float a111 = pA111 ? __ldg(pA + HW + W + 1) : 0.0f;

        float bu00 = pB100 ? __ldg(pB + HW)         : 0.0f;
        float bu01 = pB101 ? __ldg(pB + HW + 1)     : 0.0f;
        float bu10 = pB110 ? __ldg(pB + HW + W)     : 0.0f;
        float bu11 = pB111 ? __ldg(pB + HW + W + 1) : 0.0f;

        // B lower plane: shared from A's upper plane for ~88% of lanes,
        // predicated load (inactive when sh) otherwise
        float bl00 = sh ? a100 : (pB000 ? __ldg(pB)         : 0.0f);
        float bl01 = sh ? a101 : (pB001 ? __ldg(pB + 1)     : 0.0f);
        float bl10 = sh ? a110 : (pB010 ? __ldg(pB + W)     : 0.0f);
        float bl11 = sh ? a111 : (pB011 ? __ldg(pB + W + 1) : 0.0f);

        // trilinear via nested lerps (only fx/fy/fz live)
        float l0 = lerpf(lerpf(a000, a001, fxA), lerpf(a010, a011, fxA), fyA);
        float l1 = lerpf(lerpf(a100, a101, fxA), lerpf(a110, a111, fxA), fyA);
        out[obA] = lerpf(l0, l1, fzA);

        float m0 = lerpf(lerpf(bl00, bl01, fxB), lerpf(bl10, bl11, fxB), fyB);
        float m1 = lerpf(lerpf(bu00, bu01, fxB), lerpf(bu10, bu11, fxB), fyB);
        out[obA + HW] = lerpf(m0, m1, fzB);
    }

    // keep phase-1 loads out of phase-0's register window
    asm volatile("" ::: "memory");

    // ================= phase 1: channel 1 =================
    {
        const float* qA = pA + DHW;
        const float* qB = pB + DHW;

        float a000 = pA000 ? __ldg(qA)              : 0.0f;
        float a001 = pA001 ? __ldg(qA + 1)          : 0.0f;
        float a010 = pA010 ? __ldg(qA + W)          : 0.0f;
        float a011 = pA011 ? __ldg(qA + W + 1)      : 0.0f;
        float a100 = pA100 ? __ldg(qA + HW)         : 0.0f;
        float a101 = pA101 ? __ldg(qA + HW + 1)     : 0.0f;
        float a110 = pA110 ? __ldg(qA + HW + W)     : 0.0f;
        float a111 = pA111 ? __ldg(qA + HW + W + 1) : 0.0f;

        float bu00 = pB100 ? __ldg(qB + HW)         : 0.0f;
        float bu01 = pB101 ? __ldg(qB + HW + 1)     : 0.0f;
        float bu10 = pB110 ? __ldg(qB + HW + W)     : 0.0f;
        float bu11 = pB111 ? __ldg(qB + HW + W + 1) : 0.0f;

        float bl00 = sh ? a100 : (pB000 ? __ldg(qB)         : 0.0f);
        float bl01 = sh ? a101 : (pB001 ? __ldg(qB + 1)     : 0.0f);
        float bl10 = sh ? a110 : (pB010 ? __ldg(qB + W)     : 0.0f);
        float bl11 = sh ? a111 : (pB011 ? __ldg(qB + W + 1) : 0.0f);

        float l0 = lerpf(lerpf(a000, a001, fxA), lerpf(a010, a011, fxA), fyA);
        float l1 = lerpf(lerpf(a100, a101, fxA), lerpf(a110, a111, fxA), fyA);
        out[obA + DHW] = lerpf(l0, l1, fzA);

        float m0 = lerpf(lerpf(bl00, bl01, fxB), lerpf(bl10, bl11, fxB), fyB);
        float m1 = lerpf(lerpf(bu00, bu01, fxB), lerpf(bu10, bu11, fxB), fyB);
        out[obA + HW + DHW] = lerpf(m0, m1, fzB);
    }
}

extern "C" void kernel_launch(void* const* d_in, const int* in_sizes, int n_in,
                              void* d_out, int out_size)
{
    const float* src = (const float*)d_in[0];
    const float* mat = (const float*)d_in[1];
    float* out = (float*)d_out;

    dim3 block(W, 1, 1);              // 224 threads = 7 warps
    dim3 grid(1, H, B * (D / 2));     // (1, 192, 160)
    affine_grid_sample_kernel<<<grid, block>>>(src, mat, out);
}